// round 15
// baseline (speedup 1.0000x reference)
#include <cuda_runtime.h>
#include <math.h>

#define Nn 4096
#define Ee 8192
#define Mm 128
#define ND 128
#define ED 64
#define PQ 16
#define NP (Nn*PQ)
#define LAYERS 4
#define TAU 0.25f
#define FRIC 0.1f
#define MAXD 32
#define GB_NB 64
#define GB_BT 64

// ---------------- device scratch (no allocation allowed) ----------------
__device__ float g_a[Nn], g_c[Nn], g_avt[Nn], g_avu[Nn];
__device__ float g_pd0[Nn], g_pwu[Nn], g_pn[Nn], g_qd0[Nn], g_Wn[Nn];
__device__ int   g_mol[Nn];
__device__ int   g_cnt[Nn];            // zero at k1 entry; reset in kBig
__device__ int   g_adjT[MAXD * Nn];    // [slot][node] -> other-node id (coalesced)
__device__ float g_wincT[MAXD * Nn];   // [slot][node] -> edge weight
__device__ int   g_ndeg[MAXD * Nn];    // [slot][node] -> deg(other)  (written in k3)
__device__ int   g_slotU[Ee], g_slotV[Ee];
__device__ float g_p0[NP], g_q0[NP];
__device__ float g_Z[Nn], g_A[Nn];     // published zub/atp
__device__ float2 g_sc2[Nn];           // published (su2, cum2)
__device__ float g_su4[Nn];            // published su4
__device__ float g_Gm[LAYERS*Mm], g_Sm[LAYERS*Mm], g_h[Mm], g_d[Mm], g_S[LAYERS];
__device__ unsigned g_bar;             // monotonic grid-barrier counter

__device__ __forceinline__ float warp_sum(float v) {
#pragma unroll
    for (int o = 16; o; o >>= 1) v += __shfl_xor_sync(0xffffffffu, v, o);
    return v;
}
__device__ __forceinline__ float sigmoidf(float x) { return 1.f / (1.f + expf(-x)); }
__device__ __forceinline__ float fsigmoid(float x) { return 1.f / (1.f + __expf(-x)); }
__device__ __forceinline__ float fsoftplus(float x) { return fmaxf(x, 0.f) + __logf(1.f + __expf(-fabsf(x))); }

// grid barrier across GB_NB blocks; monotonic counter, busy-spin.
// Each launch consumes exactly 3*GB_NB increments (invariant % GB_NB == 0).
__device__ __forceinline__ void gsync() {
    __threadfence();
    __syncthreads();
    if (threadIdx.x == 0) {
        unsigned t = atomicAdd(&g_bar, 1u);
        unsigned target = (t / GB_NB + 1u) * GB_NB;
        while (*((volatile unsigned*)&g_bar) < target) { }
    }
    __syncthreads();
    __threadfence();
}
__device__ __forceinline__ void garrive() {
    __threadfence();
    __syncthreads();
    if (threadIdx.x == 0) atomicAdd(&g_bar, 1u);
}

// ======== k1: node setup (warp/node) + mol ids + adjacency + accumulator zeroing ========
__global__ void k1(const float* __restrict__ vf, const float* __restrict__ mnm,
                   const int* __restrict__ us, const int* __restrict__ vs,
                   const float* __restrict__ We, const float* __restrict__ Wp,
                   const float* __restrict__ bp, const float* __restrict__ Wt,
                   const float* __restrict__ Wu)
{
    int tid  = blockIdx.x * blockDim.x + threadIdx.x;   // 131072 threads
    int lane = threadIdx.x & 31;
    int n    = tid >> 5;                                 // warp -> node

    if (tid < Nn) g_Wn[tid] = 0.f;
    if (tid < LAYERS*Mm) { g_Gm[tid] = 0.f; g_Sm[tid] = 0.f; }
    if (tid < Mm) { g_h[tid] = 0.f; g_d[tid] = 0.f; }
    if (tid < LAYERS) g_S[tid] = 0.f;

    for (int idx = tid; idx < Mm * Nn; idx += 131072)
        if (mnm[idx] > 0.5f) g_mol[idx & (Nn - 1)] = idx >> 12;

    for (int e = tid; e < Ee; e += 131072) {
        int u = us[e], v = vs[e];
        int s1 = atomicAdd(&g_cnt[u], 1);
        if (s1 < MAXD) g_adjT[s1 * Nn + u] = v;
        g_slotU[e] = s1;
        if (u != v) {
            int s2 = atomicAdd(&g_cnt[v], 1);
            if (s2 < MAXD) g_adjT[s2 * Nn + v] = u;
            g_slotV[e] = s2;
        }
    }

    float v0 = vf[n*ND+lane], v1 = vf[n*ND+lane+32], v2 = vf[n*ND+lane+64], v3 = vf[n*ND+lane+96];
    float sa = warp_sum(v0*We[lane]     + v1*We[lane+32]     + v2*We[lane+64]     + v3*We[lane+96]);
    float sc = warp_sum(v0*We[192+lane] + v1*We[192+lane+32] + v2*We[192+lane+64] + v3*We[192+lane+96]);
    float st = warp_sum(v0*Wt[lane]     + v1*Wt[lane+32]     + v2*Wt[lane+64]     + v3*Wt[lane+96]);
    float su = warp_sum(v0*Wu[lane]     + v1*Wu[lane+32]     + v2*Wu[lane+64]     + v3*Wu[lane+96]);

    float pk = 0.f;
#pragma unroll
    for (int k = 0; k < PQ; k++) {
        float s = warp_sum(v0*Wp[lane*PQ+k] + v1*Wp[(lane+32)*PQ+k] +
                           v2*Wp[(lane+64)*PQ+k] + v3*Wp[(lane+96)*PQ+k]);
        if (lane == k) pk = tanhf(s + bp[k]);
    }
    float pd0 = warp_sum(lane < PQ ? pk * Wt[ND+lane] : 0.f);
    float pwu = warp_sum(lane < PQ ? pk * Wu[ND+lane] : 0.f);
    float pn  = warp_sum(lane < PQ ? pk * pk          : 0.f);
    if (lane < PQ) g_p0[n*PQ+lane] = pk;
    if (lane == 0) {
        g_a[n] = sa; g_c[n] = sc; g_avt[n] = st; g_avu[n] = su;
        g_pd0[n] = pd0; g_pwu[n] = pwu; g_pn[n] = pn;
    }
}

// ======== k2: edge weights (warp/edge) ========
__global__ void k2(const float* __restrict__ ef,
                   const int* __restrict__ us, const int* __restrict__ vs,
                   const float* __restrict__ We, const float* __restrict__ be)
{
    int e    = (blockIdx.x * blockDim.x + threadIdx.x) >> 5;
    int lane = threadIdx.x & 31;
    if (e >= Ee) return;
    float s = ef[e*ED+lane] * We[128+lane] + ef[e*ED+32+lane] * We[160+lane];
    s = warp_sum(s);
    if (lane == 0) {
        int u = us[e], v = vs[e];
        float w = sigmoidf(g_a[u] + g_c[v] + s + be[0]);
        int s1 = g_slotU[e];
        if (s1 < MAXD) g_wincT[s1 * Nn + u] = w;
        if (u != v) {
            int s2 = g_slotV[e];
            if (s2 < MAXD) g_wincT[s2 * Nn + v] = w;
            atomicAdd(&g_Wn[u], w);
            atomicAdd(&g_Wn[v], w);
        }
    }
}

// ======== k3: q0 = tanh((e@v)@Wq + bq), qd0 (warp/node) + neighbor-degree publish ========
__global__ void k3(const float* __restrict__ vf, const float* __restrict__ Wq,
                   const float* __restrict__ bq, const float* __restrict__ Wu)
{
    int n    = (blockIdx.x * blockDim.x + threadIdx.x) >> 5;
    int lane = threadIdx.x & 31;
    float x0 = vf[n*ND+lane], x1 = vf[n*ND+lane+32], x2 = vf[n*ND+lane+64], x3 = vf[n*ND+lane+96];
    float Wn = g_Wn[n];
    float e0 = Wn*x0, e1 = Wn*x1, e2 = Wn*x2, e3 = Wn*x3;
    int deg = min(g_cnt[n], MAXD);
    for (int j = 0; j < deg; j++) {
        int   o = g_adjT[j*Nn + n];
        float w = g_wincT[j*Nn + n];
        if (lane == 0) g_ndeg[j*Nn + n] = min(g_cnt[o], MAXD);
        e0 += w * vf[o*ND+lane];
        e1 += w * vf[o*ND+lane+32];
        e2 += w * vf[o*ND+lane+64];
        e3 += w * vf[o*ND+lane+96];
    }
    float qk = 0.f;
#pragma unroll
    for (int k = 0; k < PQ; k++) {
        float s = warp_sum(e0*Wq[lane*PQ+k] + e1*Wq[(lane+32)*PQ+k] +
                           e2*Wq[(lane+64)*PQ+k] + e3*Wq[(lane+96)*PQ+k]);
        if (lane == k) qk = tanhf(s + bq[k]);
    }
    float qd0 = warp_sum(lane < PQ ? qk * Wu[ND+lane] : 0.f);
    if (lane < PQ) g_q0[n*PQ+lane] = qk;
    if (lane == 0) g_qd0[n] = qd0;
}

// ======== kBig: 4 layers with TWO layers per barrier (redundant neighbor recompute) ========
__global__ void __launch_bounds__(GB_BT, 1)
kBig(const float* __restrict__ Wt, const float* __restrict__ Wu, float* __restrict__ out)
{
    __shared__ unsigned short s_o [MAXD * GB_BT];  // own neighbor ids
    __shared__ float          s_w [MAXD * GB_BT];  // own edge weights
    __shared__ unsigned short s_nd[MAXD * GB_BT];  // neighbor degrees
    __shared__ float sh[2];
    __shared__ float shPN;

    const int t = threadIdx.x;
    const int n = blockIdx.x * GB_BT + t;         // thread per node
    const int lane = t & 31;

    float nWt = 0.f, nWu = 0.f, dTU = 0.f;
    float wt2[PQ], wu2[PQ];
#pragma unroll
    for (int k = 0; k < PQ; k++) {
        float a = Wu[ND+k], b = Wt[ND+k];
        wt2[k] = b; wu2[k] = a;
        nWu += a*a; nWt += b*b; dTU += a*b;
    }

    const int   deg = min(g_cnt[n], MAXD);
    const int   mol = g_mol[n];
    const float Wn  = g_Wn[n];
    const float pd0 = g_pd0[n], pwu = g_pwu[n];

    // ---- cache own adjacency ----
    for (int j = 0; j < deg; j++) {
        s_o [j*GB_BT + t] = (unsigned short)g_adjT[j*Nn + n];
        s_w [j*GB_BT + t] = g_wincT[j*Nn + n];
        s_nd[j*GB_BT + t] = (unsigned short)g_ndeg[j*Nn + n];
    }

    // ================= Phase A: layers 1 + 2 =================
    // own zub/atp
    float zub = g_avu[n] + Wn * g_qd0[n];
    for (int j = 0; j < deg; j++)
        zub += s_w[j*GB_BT + t] * g_qd0[s_o[j*GB_BT + t]];
    const float atp = g_avt[n] + pd0;
    g_Z[n] = zub; g_A[n] = atp;

    float st1 = fsigmoid(atp), su1 = fsigmoid(zub);
    float cum1 = st1;

    // redundant neighbor L1 -> gg1, G1
    float gg1 = Wn * su1, G1 = Wn * cum1;
    for (int j = 0; j < deg; j++) {
        int   o   = s_o[j*GB_BT + t];
        float w   = s_w[j*GB_BT + t];
        int   dgo = s_nd[j*GB_BT + t];
        float zo  = g_avu[o] + g_Wn[o] * g_qd0[o];
        for (int j2 = 0; j2 < dgo; j2++)
            zo += g_wincT[j2*Nn + o] * g_qd0[g_adjT[j2*Nn + o]];
        float ao = g_avt[o] + g_pd0[o];
        gg1 += w * fsigmoid(zo);
        G1  += w * fsigmoid(ao);
    }
    float cumG = gg1;
    float st2 = fsigmoid(atp - TAU * (dTU * cumG + FRIC * nWt * cum1));
    float su2 = fsigmoid(zub + TAU * dTU * G1);
    float cum2 = cum1 + st2;
    g_sc2[n] = make_float2(su2, cum2);

    float wS = 4.f*st1 + 3.f*st2, wG = 4.f*gg1;
    atomicAdd(&g_Sm[0*Mm + mol], st1);
    atomicAdd(&g_Sm[1*Mm + mol], st2);
    atomicAdd(&g_Gm[0*Mm + mol], gg1);
    {
        float sl0 = st1*st1*nWt - 2.f*st1*pd0;
        float a1 = st2 + TAU*FRIC*cum1, b1 = TAU*cumG;
        float sl1 = a1*a1*nWt + b1*b1*nWu + 2.f*a1*b1*dTU - 2.f*a1*pd0 - 2.f*b1*pwu;
        sl0 = warp_sum(sl0); sl1 = warp_sum(sl1);
        if (lane == 0) { atomicAdd(&g_S[0], sl0); atomicAdd(&g_S[1], sl1); }
    }
    gsync();  // 1

    // ================= Phase B: layers 3 + 4 =================
    float gg2 = Wn * su2, G2 = Wn * cum2;
    float gg3 = 0.f, G3 = 0.f;
    for (int j = 0; j < deg; j++) {
        int    o   = s_o[j*GB_BT + t];
        float  w   = s_w[j*GB_BT + t];
        int    dgo = s_nd[j*GB_BT + t];
        float  Zo  = g_Z[o], Ao = g_A[o];
        float2 so  = g_sc2[o];
        float  Wno = g_Wn[o];
        gg2 += w * so.x; G2 += w * so.y;
        // redundant neighbor L3
        float gg1o = Wno * fsigmoid(Zo);
        float gg2o = Wno * so.x;
        float G2o  = Wno * so.y;
        for (int j2 = 0; j2 < dgo; j2++) {
            int    o2  = g_adjT[j2*Nn + o];
            float  w2  = g_wincT[j2*Nn + o];
            gg1o += w2 * fsigmoid(g_Z[o2]);
            float2 s22 = g_sc2[o2];
            gg2o += w2 * s22.x;
            G2o  += w2 * s22.y;
        }
        float cumG2o = gg1o + gg2o;
        float st3o = fsigmoid(Ao - TAU * (dTU * cumG2o + FRIC * nWt * so.y));
        float su3o = fsigmoid(Zo + TAU * dTU * G2o);
        float cum3o = so.y + st3o;
        gg3 += w * su3o; G3 += w * cum3o;
    }
    cumG += gg2;  // cumG2
    float st3 = fsigmoid(atp - TAU * (dTU * cumG + FRIC * nWt * cum2));
    float su3 = fsigmoid(zub + TAU * dTU * G2);
    float cum3 = cum2 + st3;
    gg3 += Wn * su3; G3 += Wn * cum3;
    atomicAdd(&g_Gm[1*Mm + mol], gg2);
    float a2 = st3 + TAU*FRIC*cum2, b2 = TAU*cumG;     // S[2] uses cumG2
    cumG += gg3;  // cumG3
    atomicAdd(&g_Gm[2*Mm + mol], gg3);
    float zt4 = atp - TAU * (dTU * cumG + FRIC * nWt * cum3);
    float st4 = fsigmoid(zt4);
    float zu4 = zub + TAU * dTU * G3;
    float su4v = fsigmoid(zu4);
    g_su4[n] = su4v;
    atomicAdd(&g_Sm[2*Mm + mol], st3);
    atomicAdd(&g_Sm[3*Mm + mol], st4);
    atomicAdd(&g_h[mol], fsoftplus(zt4) + fsoftplus(zu4));
    atomicAdd(&g_d[mol], st4 * st4);
    wS += 2.f*st3 + st4; wG += 3.f*gg2 + 2.f*gg3;
    {
        float sl2 = a2*a2*nWt + b2*b2*nWu + 2.f*a2*b2*dTU - 2.f*a2*pd0 - 2.f*b2*pwu;
        float a3 = st4 + TAU*FRIC*cum3, b3 = TAU*cumG;
        float sl3 = a3*a3*nWt + b3*b3*nWu + 2.f*a3*b3*dTU - 2.f*a3*pd0 - 2.f*b3*pwu;
        sl2 = warp_sum(sl2); sl3 = warp_sum(sl3);
        if (lane == 0) { atomicAdd(&g_S[2], sl2); atomicAdd(&g_S[3], sl3); }
    }
    gsync();  // 2

    // ================= Phase C: gg4 + outputs =================
    float gg4 = Wn * su4v;
    for (int j = 0; j < deg; j++)
        gg4 += s_w[j*GB_BT + t] * g_su4[s_o[j*GB_BT + t]];
    atomicAdd(&g_Gm[3*Mm + mol], gg4);
    wG += gg4;

    {
        float cp1 = -(TAU*FRIC) * wS, cp2 = -TAU * wG, cq = TAU * wS;
#pragma unroll
        for (int k = 0; k < PQ; k++) {
            out[n*PQ + k]      = 0.2f * (5.f*g_p0[n*PQ+k] + cp1*wt2[k] + cp2*wu2[k]);
            out[NP + n*PQ + k] = 0.2f * (5.f*g_q0[n*PQ+k] + cq*wt2[k]);
        }
    }
    g_cnt[n] = 0;

    if (blockIdx.x == 0) gsync();   // 3: epilogue block must see all atomics
    else { garrive(); return; }

    // ---- block 0: scalars + h/d ----
    {
        float pn = 0.f;
        for (int i = t; i < Nn; i += GB_BT) pn += g_pn[i];
        pn = warp_sum(pn);
        if (lane == 0) sh[t >> 5] = pn;
        __syncthreads();
        if (t == 0) shPN = sh[0] + sh[1];
        __syncthreads();
        if (t < 32) {
            float cT = 0.f;
            for (int i = 0; i < LAYERS; i++) {
                float term = 0.f;
                for (int m = lane; m < Mm; m += 32) {
                    float Gm = g_Gm[i*Mm+m], Sm = g_Sm[i*Mm+m];
                    term += Gm*Gm*nWu + 2.f*FRIC*Gm*Sm*dTU + FRIC*FRIC*Sm*Sm*nWt;
                }
                term = warp_sum(term);
                cT += TAU * sqrtf(term);
            }
            if (lane == 0) {
                float sT = 0.f;
                for (int i = 0; i < LAYERS; i++) sT += sqrtf(g_S[i] + shPN);
                out[2*NP + 0] = sT;
                out[2*NP + 1] = cT;
            }
        }
        for (int m = t; m < Mm; m += GB_BT) {
            out[2*NP + 2 + m]      = g_h[m];
            out[2*NP + 2 + Mm + m] = g_d[m] * nWt;
        }
    }
}

extern "C" void kernel_launch(void* const* d_in, const int* in_sizes, int n_in,
                              void* d_out, int out_size)
{
    const float* vf  = (const float*)d_in[0];
    const float* ef  = (const float*)d_in[1];
    const int*   us  = (const int*)  d_in[2];
    const int*   vs  = (const int*)  d_in[3];
    const float* mnm = (const float*)d_in[4];
    const float* We  = (const float*)d_in[8];
    const float* be  = (const float*)d_in[9];
    const float* Wp  = (const float*)d_in[10];
    const float* bp  = (const float*)d_in[11];
    const float* Wq  = (const float*)d_in[12];
    const float* bq  = (const float*)d_in[13];
    const float* Wt  = (const float*)d_in[14];
    const float* Wu  = (const float*)d_in[15];
    float* out = (float*)d_out;

    k1<<<512, 256>>>(vf, mnm, us, vs, We, Wp, bp, Wt, Wu);
    k2<<<1024, 256>>>(ef, us, vs, We, be);
    k3<<<512, 256>>>(vf, Wq, bq, Wu);
    kBig<<<GB_NB, GB_BT>>>(Wt, Wu, out);
}